// round 6
// baseline (speedup 1.0000x reference)
#include <cuda_runtime.h>

#define MAXN 100000
#define F 64

// Scratch (allocation-free rule: __device__ globals).
// Double-buffered per layer so no kernel ever reads a buffer it also writes.
__device__ int   g_degi[MAXN];
__device__ float g_dinv[MAXN];
__device__ float g_hs1[(size_t)MAXN * F];
__device__ float g_acc1[(size_t)MAXN * F];
__device__ float g_hs2[(size_t)MAXN * F];
__device__ float g_acc2[(size_t)MAXN * F];

__global__ void k_deg_init(int N) {
    int i = blockIdx.x * blockDim.x + threadIdx.x;
    if (i < N) g_degi[i] = 0;
}

__global__ void k_deg_count(const int* __restrict__ dst, int E) {
    int e = blockIdx.x * blockDim.x + threadIdx.x;
    if (e < E) atomicAdd(&g_degi[dst[e]], 1);
}

__global__ void k_dinv(int N) {
    int i = blockIdx.x * blockDim.x + threadIdx.x;
    if (i < N) g_dinv[i] = rsqrtf(1.0f + (float)g_degi[i]);  // +1 self-loop
}

// Scatter: acc[dst] += hs[src].  acc was pre-initialized to hs (self-loop term)
// by the producing GEMM, and dinv[src] is already folded into hs; dinv[dst] is
// applied by the consuming GEMM. 16 threads/edge, float4 each -> coalesced
// 256B row gather + vector RED.
__global__ void k_scatter(const int* __restrict__ src, const int* __restrict__ dst,
                          const float* __restrict__ hs, float* __restrict__ acc, int E) {
    int t = blockIdx.x * blockDim.x + threadIdx.x;
    int e = t >> 4;
    if (e >= E) return;
    int c = t & 15;
    int s = src[e];
    int d = dst[e];
    float4 v = *(const float4*)&hs[(size_t)s * F + c * 4];
    float* p = &acc[(size_t)d * F + c * 4];
    asm volatile("red.global.add.v4.f32 [%0], {%1,%2,%3,%4};"
                 :: "l"(p), "f"(v.x), "f"(v.y), "f"(v.z), "f"(v.w)
                 : "memory");
}

// Fused GEMM, split-output: 256 threads = 128 rows x 2 output-halves.
// Each thread computes NOUT/2 outputs for one row (32 accumulators -> high occ).
//  MODE 0: in = x[row];                 hs_out = acc_out = (in@W)*dinv
//  MODE 1: in = relu(dinv*acc_in + b);  hs_out = acc_out = (in@W)*dinv
//  MODE 2: in = relu(dinv*acc_in + b);  out = in@W + b_out   (NOUT=32)
// All reads (acc_in) and writes (hs_out/acc_out) target DIFFERENT buffers,
// so there is no intra-kernel cross-warp hazard.
template <int NOUT, int MODE>
__global__ void __launch_bounds__(256, 4)
k_gemm(const float* __restrict__ xin, const float* __restrict__ W,
       const float* __restrict__ b_in, const float* __restrict__ b_out,
       const float* __restrict__ acc_in,
       float* __restrict__ hs_out, float* __restrict__ acc_out,
       float* __restrict__ out, int N) {
    constexpr int HALF = NOUT / 2;
    __shared__ float sW[F * NOUT];
    {
        const float4* W4 = (const float4*)W;
        float4* sW4 = (float4*)sW;
        for (int i = threadIdx.x; i < F * NOUT / 4; i += 256) sW4[i] = W4[i];
    }
    __syncthreads();

    int lane = threadIdx.x & 127;   // row within block
    int half = threadIdx.x >> 7;    // which half of the outputs
    int row = blockIdx.x * 128 + lane;
    if (row >= N) return;

    float racc[HALF];
#pragma unroll
    for (int j = 0; j < HALF; j++) racc[j] = 0.0f;

    float d = g_dinv[row];
    const float4* xr4 = (const float4*)(xin + (size_t)row * F);
    const float4* ar4 = (const float4*)(acc_in + (size_t)row * F);
    const float4* b4  = (const float4*)b_in;

#pragma unroll
    for (int kk = 0; kk < F / 4; kk++) {
        float4 xv;
        if (MODE == 0) {
            xv = xr4[kk];
        } else {
            float4 a = ar4[kk], bb = b4[kk];
            xv.x = fmaxf(fmaf(d, a.x, bb.x), 0.0f);
            xv.y = fmaxf(fmaf(d, a.y, bb.y), 0.0f);
            xv.z = fmaxf(fmaf(d, a.z, bb.z), 0.0f);
            xv.w = fmaxf(fmaf(d, a.w, bb.w), 0.0f);
        }
        float vk[4] = {xv.x, xv.y, xv.z, xv.w};
#pragma unroll
        for (int u = 0; u < 4; u++) {
            const float4* wr = (const float4*)&sW[(kk * 4 + u) * NOUT + half * HALF];
            float v = vk[u];
#pragma unroll
            for (int j = 0; j < HALF / 4; j++) {
                float4 w = wr[j];
                racc[4 * j + 0] = fmaf(v, w.x, racc[4 * j + 0]);
                racc[4 * j + 1] = fmaf(v, w.y, racc[4 * j + 1]);
                racc[4 * j + 2] = fmaf(v, w.z, racc[4 * j + 2]);
                racc[4 * j + 3] = fmaf(v, w.w, racc[4 * j + 3]);
            }
        }
    }

    if (MODE == 2) {
        float4* o4 = (float4*)(out + (size_t)row * NOUT + half * HALF);
        const float4* bo4 = (const float4*)(b_out + half * HALF);
#pragma unroll
        for (int j = 0; j < HALF / 4; j++) {
            float4 bo = bo4[j];
            float4 r;
            r.x = racc[4 * j + 0] + bo.x;
            r.y = racc[4 * j + 1] + bo.y;
            r.z = racc[4 * j + 2] + bo.z;
            r.w = racc[4 * j + 3] + bo.w;
            o4[j] = r;
        }
    } else {
        float4* hw4 = (float4*)(hs_out + (size_t)row * F + half * HALF);
        float4* aw4 = (float4*)(acc_out + (size_t)row * F + half * HALF);
#pragma unroll
        for (int j = 0; j < HALF / 4; j++) {
            float4 r;
            r.x = racc[4 * j + 0] * d;
            r.y = racc[4 * j + 1] * d;
            r.z = racc[4 * j + 2] * d;
            r.w = racc[4 * j + 3] * d;
            hw4[j] = r;
            aw4[j] = r;  // acc starts at self-contribution hs; scatter adds on top
        }
    }
}

extern "C" void kernel_launch(void* const* d_in, const int* in_sizes, int n_in,
                              void* d_out, int out_size) {
    const float* x  = (const float*)d_in[0];
    const int*   ei = (const int*)d_in[1];
    const float* W1 = (const float*)d_in[2];
    const float* b1 = (const float*)d_in[3];
    const float* W2 = (const float*)d_in[4];
    const float* b2 = (const float*)d_in[5];
    const float* Wl = (const float*)d_in[6];
    const float* bl = (const float*)d_in[7];
    float* out = (float*)d_out;

    int N = in_sizes[0] / F;
    int E = in_sizes[1] / 2;
    const int* src = ei;
    const int* dst = ei + E;

    int nb256 = (N + 255) / 256;
    int nb128 = (N + 127) / 128;
    int eb = (E + 255) / 256;
    long long st = (long long)E * 16;
    int sb = (int)((st + 255) / 256);

    float* hs1  = g_hs1;  float* acc1 = g_acc1;
    float* hs2  = g_hs2;  float* acc2 = g_acc2;

    // degree + dinv (recomputed each launch; deterministic)
    k_deg_init<<<nb256, 256>>>(N);
    k_deg_count<<<eb, 256>>>(dst, E);
    k_dinv<<<nb256, 256>>>(N);

    // layer 1: hs1 = acc1 = (x@W1)*dinv ; scatter into acc1
    k_gemm<F, 0><<<nb128, 256>>>(x, W1, nullptr, nullptr, nullptr, hs1, acc1, nullptr, N);
    k_scatter<<<sb, 256>>>(src, dst, hs1, acc1, E);

    // layer 2: in = relu(dinv*acc1 + b1); hs2 = acc2 = (in@W2)*dinv ; scatter into acc2
    k_gemm<F, 1><<<nb128, 256>>>(nullptr, W2, b1, nullptr, acc1, hs2, acc2, nullptr, N);
    k_scatter<<<sb, 256>>>(src, dst, hs2, acc2, E);

    // head: in = relu(dinv*acc2 + b2); out = in@Wl + bl
    k_gemm<32, 2><<<nb128, 256>>>(nullptr, Wl, b2, bl, acc2, nullptr, nullptr, out, N);
}

// round 7
// speedup vs baseline: 32.8399x; 32.8399x over previous
#include <cuda_runtime.h>

#define MAXN 100000
#define F 64

// Scratch (allocation-free rule: __device__ globals).
// Double-buffered per layer so no kernel ever reads a buffer it also writes.
// IMPORTANT: these symbols are referenced ONLY inside device code. Taking
// their address in host code yields the host shadow symbol, which on GB300
// (ATS) silently routes all traffic over NVLink-C2C -> 34x slowdown.
__device__ int   g_degi[MAXN];
__device__ float g_dinv[MAXN];
__device__ float g_hs1[(size_t)MAXN * F];
__device__ float g_acc1[(size_t)MAXN * F];
__device__ float g_hs2[(size_t)MAXN * F];
__device__ float g_acc2[(size_t)MAXN * F];

// Device-side buffer selection (compile-time)
template <int L> __device__ __forceinline__ const float* hs_in()  { return L == 1 ? g_hs1 : g_hs2; }
template <int L> __device__ __forceinline__ float*       hs_out() { return L == 1 ? g_hs1 : g_hs2; }
template <int L> __device__ __forceinline__ float*       acc_rw() { return L == 1 ? g_acc1 : g_acc2; }

__global__ void k_deg_init(int N) {
    int i = blockIdx.x * blockDim.x + threadIdx.x;
    if (i < N) g_degi[i] = 0;
}

__global__ void k_deg_count(const int* __restrict__ dst, int E) {
    int e = blockIdx.x * blockDim.x + threadIdx.x;
    if (e < E) atomicAdd(&g_degi[dst[e]], 1);
}

__global__ void k_dinv(int N) {
    int i = blockIdx.x * blockDim.x + threadIdx.x;
    if (i < N) g_dinv[i] = rsqrtf(1.0f + (float)g_degi[i]);  // +1 self-loop
}

// Scatter: acc[dst] += hs[src].  acc was pre-initialized to hs (self-loop term)
// by the producing GEMM; dinv[src] is already folded into hs; dinv[dst] is
// applied by the consuming GEMM. 16 threads/edge, float4 each -> coalesced
// 256B row gather + vector RED.
template <int L>
__global__ void k_scatter(const int* __restrict__ src, const int* __restrict__ dst, int E) {
    const float* hs = hs_in<L>();
    float* acc = acc_rw<L>();
    int t = blockIdx.x * blockDim.x + threadIdx.x;
    int e = t >> 4;
    if (e >= E) return;
    int c = t & 15;
    int s = src[e];
    int d = dst[e];
    float4 v = *(const float4*)&hs[(size_t)s * F + c * 4];
    float* p = &acc[(size_t)d * F + c * 4];
    asm volatile("red.global.add.v4.f32 [%0], {%1,%2,%3,%4};"
                 :: "l"(p), "f"(v.x), "f"(v.y), "f"(v.z), "f"(v.w)
                 : "memory");
}

// Fused GEMM, split-output: 256 threads = 128 rows x 2 output-halves.
// Each thread computes NOUT/2 outputs for one row (32 accumulators -> high occ).
//  MODE 0: in = x[row];                 g_hs1 = g_acc1 = (in@W)*dinv
//  MODE 1: in = relu(dinv*g_acc1 + b);  g_hs2 = g_acc2 = (in@W)*dinv
//  MODE 2: in = relu(dinv*g_acc2 + b);  out = in@W + b_out   (NOUT=32)
// Reads and writes always target DIFFERENT buffers -> no cross-warp hazard.
template <int NOUT, int MODE>
__global__ void __launch_bounds__(256, 4)
k_gemm(const float* __restrict__ xin, const float* __restrict__ W,
       const float* __restrict__ b_in, const float* __restrict__ b_out,
       float* __restrict__ out, int N) {
    constexpr int HALF = NOUT / 2;
    __shared__ float sW[F * NOUT];
    {
        const float4* W4 = (const float4*)W;
        float4* sW4 = (float4*)sW;
        for (int i = threadIdx.x; i < F * NOUT / 4; i += 256) sW4[i] = W4[i];
    }
    __syncthreads();

    int lane = threadIdx.x & 127;   // row within block
    int half = threadIdx.x >> 7;    // which half of the outputs
    int row = blockIdx.x * 128 + lane;
    if (row >= N) return;

    float racc[HALF];
#pragma unroll
    for (int j = 0; j < HALF; j++) racc[j] = 0.0f;

    float d = g_dinv[row];
    const float* acc_src = (MODE == 1) ? g_acc1 : g_acc2;  // MODE 0 unused
    const float4* xr4 = (const float4*)(xin + (size_t)row * F);
    const float4* ar4 = (const float4*)(acc_src + (size_t)row * F);
    const float4* b4  = (const float4*)b_in;

#pragma unroll
    for (int kk = 0; kk < F / 4; kk++) {
        float4 xv;
        if (MODE == 0) {
            xv = xr4[kk];
        } else {
            float4 a = ar4[kk], bb = b4[kk];
            xv.x = fmaxf(fmaf(d, a.x, bb.x), 0.0f);
            xv.y = fmaxf(fmaf(d, a.y, bb.y), 0.0f);
            xv.z = fmaxf(fmaf(d, a.z, bb.z), 0.0f);
            xv.w = fmaxf(fmaf(d, a.w, bb.w), 0.0f);
        }
        float vk[4] = {xv.x, xv.y, xv.z, xv.w};
#pragma unroll
        for (int u = 0; u < 4; u++) {
            const float4* wr = (const float4*)&sW[(kk * 4 + u) * NOUT + half * HALF];
            float v = vk[u];
#pragma unroll
            for (int j = 0; j < HALF / 4; j++) {
                float4 w = wr[j];
                racc[4 * j + 0] = fmaf(v, w.x, racc[4 * j + 0]);
                racc[4 * j + 1] = fmaf(v, w.y, racc[4 * j + 1]);
                racc[4 * j + 2] = fmaf(v, w.z, racc[4 * j + 2]);
                racc[4 * j + 3] = fmaf(v, w.w, racc[4 * j + 3]);
            }
        }
    }

    if (MODE == 2) {
        float4* o4 = (float4*)(out + (size_t)row * NOUT + half * HALF);
        const float4* bo4 = (const float4*)(b_out + half * HALF);
#pragma unroll
        for (int j = 0; j < HALF / 4; j++) {
            float4 bo = bo4[j];
            float4 r;
            r.x = racc[4 * j + 0] + bo.x;
            r.y = racc[4 * j + 1] + bo.y;
            r.z = racc[4 * j + 2] + bo.z;
            r.w = racc[4 * j + 3] + bo.w;
            o4[j] = r;
        }
    } else {
        float* hsw  = (MODE == 0) ? g_hs1 : g_hs2;
        float* accw = (MODE == 0) ? g_acc1 : g_acc2;
        float4* hw4 = (float4*)(hsw  + (size_t)row * F + half * HALF);
        float4* aw4 = (float4*)(accw + (size_t)row * F + half * HALF);
#pragma unroll
        for (int j = 0; j < HALF / 4; j++) {
            float4 r;
            r.x = racc[4 * j + 0] * d;
            r.y = racc[4 * j + 1] * d;
            r.z = racc[4 * j + 2] * d;
            r.w = racc[4 * j + 3] * d;
            hw4[j] = r;
            aw4[j] = r;  // acc starts at self-contribution hs; scatter adds on top
        }
    }
}

extern "C" void kernel_launch(void* const* d_in, const int* in_sizes, int n_in,
                              void* d_out, int out_size) {
    const float* x  = (const float*)d_in[0];
    const int*   ei = (const int*)d_in[1];
    const float* W1 = (const float*)d_in[2];
    const float* b1 = (const float*)d_in[3];
    const float* W2 = (const float*)d_in[4];
    const float* b2 = (const float*)d_in[5];
    const float* Wl = (const float*)d_in[6];
    const float* bl = (const float*)d_in[7];
    float* out = (float*)d_out;

    int N = in_sizes[0] / F;
    int E = in_sizes[1] / 2;
    const int* src = ei;
    const int* dst = ei + E;

    int nb256 = (N + 255) / 256;
    int nb128 = (N + 127) / 128;
    int eb = (E + 255) / 256;
    long long st = (long long)E * 16;
    int sb = (int)((st + 255) / 256);

    // degree + dinv (recomputed each launch; deterministic)
    k_deg_init<<<nb256, 256>>>(N);
    k_deg_count<<<eb, 256>>>(dst, E);
    k_dinv<<<nb256, 256>>>(N);

    // layer 1: hs1 = acc1 = (x@W1)*dinv ; scatter into acc1
    k_gemm<F, 0><<<nb128, 256>>>(x, W1, nullptr, nullptr, nullptr, N);
    k_scatter<1><<<sb, 256>>>(src, dst, E);

    // layer 2: in = relu(dinv*acc1 + b1); hs2 = acc2 = (in@W2)*dinv ; scatter into acc2
    k_gemm<F, 1><<<nb128, 256>>>(nullptr, W2, b1, nullptr, nullptr, N);
    k_scatter<2><<<sb, 256>>>(src, dst, E);

    // head: in = relu(dinv*acc2 + b2); out = in@Wl + bl
    k_gemm<32, 2><<<nb128, 256>>>(nullptr, Wl, b2, bl, out, N);
}